// round 14
// baseline (speedup 1.0000x reference)
#include <cuda_runtime.h>
#include <cuda_pipeline.h>
#include <cuda_fp16.h>
#include <math.h>
#include <stdint.h>

#define LQ     4096
#define DMODEL 1024
#define NH     16
#define NKV    4
#define DHD    64
#define NQKV   1536   // 1024 q + 256 k + 256 v
#define KVD    256

// ------------------------- scratch (device globals, no allocs) ---------------
__device__ __half g_xh[LQ*DMODEL];
__device__ __half g_wch[DMODEL*NQKV];      // packed [K, Nq|Nk|Nv]
__device__ __half g_woh[DMODEL*DMODEL];
__device__ __half g_qkvh[LQ*NQKV];
__device__ __half g_ah[LQ*DMODEL];
__device__ float  g_cos[LQ*32], g_sin[LQ*32];

// ------------------------- fused fp16 convert (x + all weights) --------------
#define CV_X  (LQ*DMODEL)
#define CV_WQ (DMODEL*DMODEL)
#define CV_WK (DMODEL*256)
#define CV_TOT (CV_X + CV_WQ + 2*CV_WK + CV_WQ)

__global__ void convert_all_kernel(const float* __restrict__ x,
                                   const float* __restrict__ Wq,
                                   const float* __restrict__ Wk,
                                   const float* __restrict__ Wv,
                                   const float* __restrict__ Wo,
                                   __half* __restrict__ xh,
                                   __half* __restrict__ wch,
                                   __half* __restrict__ woh) {
    for (int i = blockIdx.x * blockDim.x + threadIdx.x; i < CV_TOT;
         i += gridDim.x * blockDim.x) {
        int j = i;
        if (j < CV_X) { xh[j] = __float2half(x[j]); continue; }
        j -= CV_X;
        if (j < CV_WQ) {
            int r = j >> 10, c = j & 1023;
            wch[(size_t)r * NQKV + c] = __float2half(Wq[j]);
            continue;
        }
        j -= CV_WQ;
        if (j < CV_WK) {
            int r = j >> 8, c = j & 255;
            wch[(size_t)r * NQKV + 1024 + c] = __float2half(Wk[j]);
            continue;
        }
        j -= CV_WK;
        if (j < CV_WK) {
            int r = j >> 8, c = j & 255;
            wch[(size_t)r * NQKV + 1280 + c] = __float2half(Wv[j]);
            continue;
        }
        j -= CV_WK;
        woh[j] = __float2half(Wo[j]);
    }
}

// ------------------------- trig table (fast-math proof) ----------------------
__global__ void trig_kernel(float* __restrict__ ct, float* __restrict__ st) {
    int idx = blockIdx.x * blockDim.x + threadIdx.x;
    if (idx >= LQ * 32) return;
    int l = idx >> 5;
    int d = idx & 31;
    double p = pow(10000.0, (double)(2 * d) / 64.0);
    float invf = (float)(1.0 / p);
    float af = __fmul_rn((float)l, invf);   // same fp32 rounding as reference
    double dv = (double)af;
    ct[idx] = (float)cos(dv);
    st[idx] = (float)sin(dv);
}

// ------------------------- raw mma / ldmatrix / ex2 helpers ------------------
__device__ __forceinline__ void mma16816_f32(float* c, const uint32_t* a,
                                             const uint32_t* b) {
    asm volatile(
        "mma.sync.aligned.m16n8k16.row.col.f32.f16.f16.f32 "
        "{%0,%1,%2,%3}, {%4,%5,%6,%7}, {%8,%9}, {%0,%1,%2,%3};"
        : "+f"(c[0]), "+f"(c[1]), "+f"(c[2]), "+f"(c[3])
        : "r"(a[0]), "r"(a[1]), "r"(a[2]), "r"(a[3]), "r"(b[0]), "r"(b[1]));
}

__device__ __forceinline__ void mma16816_f16(uint32_t* c, const uint32_t* a,
                                             const uint32_t* b) {
    asm volatile(
        "mma.sync.aligned.m16n8k16.row.col.f16.f16.f16.f16 "
        "{%0,%1}, {%2,%3,%4,%5}, {%6,%7}, {%0,%1};"
        : "+r"(c[0]), "+r"(c[1])
        : "r"(a[0]), "r"(a[1]), "r"(a[2]), "r"(a[3]), "r"(b[0]), "r"(b[1]));
}

__device__ __forceinline__ uint32_t ex2_f16x2(uint32_t v) {
    uint32_t r;
    asm("ex2.approx.f16x2 %0, %1;" : "=r"(r) : "r"(v));
    return r;
}

__device__ __forceinline__ void ldsm_x4(uint32_t* r, uint32_t saddr) {
    asm volatile(
        "ldmatrix.sync.aligned.m8n8.x4.shared.b16 {%0,%1,%2,%3}, [%4];"
        : "=r"(r[0]), "=r"(r[1]), "=r"(r[2]), "=r"(r[3]) : "r"(saddr));
}

__device__ __forceinline__ void ldsm_x4_t(uint32_t* r, uint32_t saddr) {
    asm volatile(
        "ldmatrix.sync.aligned.m8n8.x4.trans.shared.b16 {%0,%1,%2,%3}, [%4];"
        : "=r"(r[0]), "=r"(r[1]), "=r"(r[2]), "=r"(r[3]) : "r"(saddr));
}

// ------------------------- raw-mma fp16 GEMM, 128x128, BK=32, 3-stage --------
// MODE 0: float C.  MODE 1: __half C.  MODE 2: __half C + fused RoPE epilogue
// (qkv layout: cols<1024 q rotate+scale, 1024..1279 k rotate, >=1280 v plain).
#define GA_LD 40
#define GB_LD 136
#define GA_SZ (128*GA_LD)
#define GB_SZ (32*GB_LD)
#define GSTG  (GA_SZ + GB_SZ)
#define GEMM_SMEM (3*GSTG*(int)sizeof(__half))

template <int MODE>
__global__ __launch_bounds__(256, 2) void gemm_raw_kernel(
    const __half* __restrict__ A, const __half* __restrict__ B,
    void* __restrict__ Cv, int K, int ldn,
    const float* __restrict__ ct, const float* __restrict__ st) {
    extern __shared__ __half smem[];
    int tid = threadIdx.x;
    int w = tid >> 5;
    int lane = tid & 31;
    int qd = lane >> 2, tq = lane & 3;
    int bm = blockIdx.y * 128, bn = blockIdx.x * 128;
    int wrow = (w >> 1) * 32, wcol = (w & 1) * 64;

    int lm = lane >> 3, r8 = lane & 7;
    int aoff = (((lm & 1) << 3) + r8) * GA_LD + ((lm >> 1) << 3);
    int boff = (((lm & 1) << 3) + r8) * GB_LD + ((lm >> 1) << 3);
    uint32_t sbase = (uint32_t)__cvta_generic_to_shared(smem);

    float c[2][8][4];
#pragma unroll
    for (int mr = 0; mr < 2; mr++)
#pragma unroll
        for (int nt = 0; nt < 8; nt++)
#pragma unroll
            for (int i = 0; i < 4; i++) c[mr][nt][i] = 0.0f;

    auto prefetch = [&](int kb, int stg) {
        __half* sA = smem + stg * GSTG;
        __half* sB = sA + GA_SZ;
#pragma unroll
        for (int p = 0; p < 2; p++) {
            int i = tid + p * 256;
            int ar = i >> 2, ac = (i & 3) * 8;
            __pipeline_memcpy_async(&sA[ar * GA_LD + ac],
                                    &A[(size_t)(bm + ar) * K + kb * 32 + ac], 16);
            int br = i >> 4, bc = (i & 15) * 8;
            __pipeline_memcpy_async(&sB[br * GB_LD + bc],
                                    &B[(size_t)(kb * 32 + br) * ldn + bn + bc], 16);
        }
    };

    int nk = K / 32;
    prefetch(0, 0);
    __pipeline_commit();
    prefetch(1, 1);
    __pipeline_commit();

    for (int kb = 0; kb < nk; kb++) {
        __pipeline_wait_prior(kb + 1 < nk ? 1 : 0);
        __syncthreads();

        if (kb + 2 < nk) {
            prefetch(kb + 2, (kb + 2) % 3);
            __pipeline_commit();
        }

        uint32_t st_ = sbase + (uint32_t)((kb % 3) * GSTG * 2);
        uint32_t sa = st_;
        uint32_t sb = st_ + GA_SZ * 2;

#pragma unroll
        for (int ks = 0; ks < 2; ks++) {
            uint32_t a[2][4];
#pragma unroll
            for (int mr = 0; mr < 2; mr++)
                ldsm_x4(a[mr], sa + (uint32_t)(((wrow + mr * 16) * GA_LD +
                                                ks * 16 + aoff) * 2));
            uint32_t b[16];
#pragma unroll
            for (int nt2 = 0; nt2 < 4; nt2++)
                ldsm_x4_t(b + nt2 * 4,
                          sb + (uint32_t)(((ks * 16) * GB_LD + wcol +
                                           nt2 * 16 + boff) * 2));
#pragma unroll
            for (int mr = 0; mr < 2; mr++)
#pragma unroll
                for (int nt = 0; nt < 8; nt++)
                    mma16816_f32(c[mr][nt], a[mr],
                                 b + (nt >> 1) * 4 + (nt & 1) * 2);
        }
    }

    // fused RoPE on accumulators (MODE 2): pair (d, d+32) == tiles (nt, nt+4)
    if (MODE == 2) {
        int colbase = bn + wcol;            // 64-aligned -> one head per window
        if (colbase < 1280) {               // q or k (v windows pass through)
            const float QS = 1.4426950408889634f / 8.0f;  // log2(e)/sqrt(DH)
            float qs = (colbase < 1024) ? QS : 1.0f;
#pragma unroll
            for (int mr = 0; mr < 2; mr++) {
                int r0 = bm + wrow + mr * 16 + qd;
#pragma unroll
                for (int nt = 0; nt < 4; nt++) {
                    int d = nt * 8 + tq * 2;
#pragma unroll
                    for (int half_ = 0; half_ < 2; half_++) {
                        int r = r0 + half_ * 8;
                        int i0 = 2 * half_;
#pragma unroll
                        for (int e = 0; e < 2; e++) {
                            float cc = ct[r * 32 + d + e];
                            float ss = st[r * 32 + d + e];
                            float av = c[mr][nt][i0 + e];
                            float bv = c[mr][nt + 4][i0 + e];
                            c[mr][nt][i0 + e]     = (av * cc - bv * ss) * qs;
                            c[mr][nt + 4][i0 + e] = (bv * cc + av * ss) * qs;
                        }
                    }
                }
            }
        }
    }

#pragma unroll
    for (int mr = 0; mr < 2; mr++) {
        int r0 = bm + wrow + mr * 16 + qd;
#pragma unroll
        for (int nt = 0; nt < 8; nt++) {
            int col = bn + wcol + nt * 8 + tq * 2;
            if (MODE != 0) {
                __half* C = (__half*)Cv;
                *(__half2*)&C[(size_t)r0 * ldn + col] =
                    __floats2half2_rn(c[mr][nt][0], c[mr][nt][1]);
                *(__half2*)&C[(size_t)(r0 + 8) * ldn + col] =
                    __floats2half2_rn(c[mr][nt][2], c[mr][nt][3]);
            } else {
                float* C = (float*)Cv;
                *(float2*)&C[(size_t)r0 * ldn + col] =
                    make_float2(c[mr][nt][0], c[mr][nt][1]);
                *(float2*)&C[(size_t)(r0 + 8) * ldn + col] =
                    make_float2(c[mr][nt][2], c[mr][nt][3]);
            }
        }
    }
}

// ------------------------- attention (FA2; V via ldmatrix.trans) -------------
// K and V tiles both [64 kv][72] row-major straight from qkvh; no vt buffer.
#define KV_LD  72
#define KV_STG (64*KV_LD)
#define FLASH_SMEM (4*KV_STG*(int)sizeof(__half))

__global__ __launch_bounds__(256, 2) void flash_kernel(
    const __half* __restrict__ qkvh, __half* __restrict__ oh) {
    extern __shared__ __half sm[];
    __half* Ks0 = sm;
    __half* Vs0 = sm + 2 * KV_STG;

    int tid = threadIdx.x;
    int w = tid >> 5;
    int lane = tid & 31;
    int qd = lane >> 2;
    int tq = lane & 3;
    int qt = blockIdx.x;
    int h = blockIdx.y;
    int kvh = h >> 2;

    int lm = lane >> 3, r8 = lane & 7;
    // K: non-trans ldsm (B of S-mma, row-major [kv][d], kv = n-dim)
    uint32_t koff = (uint32_t)(((r8 * KV_LD) + (lm << 3)) * 2);
    // V: trans ldsm (B of PV-mma, row-major [kv][d], kv = k-dim)
    uint32_t voff = (uint32_t)(((((lm & 1) << 3) + r8) * KV_LD +
                               ((lm >> 1) << 3)) * 2);
    uint32_t ks_base0 = (uint32_t)__cvta_generic_to_shared(Ks0) + koff;
    uint32_t vs_base0 = (uint32_t)__cvta_generic_to_shared(Vs0) + voff;

    uint32_t qf[4][4];
    {
        int r0 = qt * 128 + w * 16 + qd;
        const __half* qb = qkvh + (size_t)r0 * NQKV + h * 64 + tq * 2;
#pragma unroll
        for (int ks = 0; ks < 4; ks++) {
            qf[ks][0] = *(const uint32_t*)(qb + ks * 16);
            qf[ks][1] = *(const uint32_t*)(qb + (size_t)8 * NQKV + ks * 16);
            qf[ks][2] = *(const uint32_t*)(qb + ks * 16 + 8);
            qf[ks][3] = *(const uint32_t*)(qb + (size_t)8 * NQKV + ks * 16 + 8);
        }
    }

    float oacc[8][4];
#pragma unroll
    for (int nt = 0; nt < 8; nt++)
#pragma unroll
        for (int i = 0; i < 4; i++) oacc[nt][i] = 0.0f;
    float lsum0 = 0.0f, lsum1 = 0.0f;

    auto kv_prefetch = [&](int kc, int s) {
        __half* Ks_ = Ks0 + s * KV_STG;
        __half* Vs_ = Vs0 + s * KV_STG;
#pragma unroll
        for (int p = 0; p < 2; p++) {
            int i = tid + p * 256;
            int r = i >> 3, c8 = (i & 7) * 8;
            size_t rb = (size_t)(kc * 64 + r) * NQKV + 1024 + kvh * 64 + c8;
            __pipeline_memcpy_async(&Ks_[r * KV_LD + c8], &qkvh[rb], 16);
            __pipeline_memcpy_async(&Vs_[r * KV_LD + c8], &qkvh[rb + 256], 16);
        }
    };

    kv_prefetch(0, 0);
    __pipeline_commit();

    for (int kc = 0; kc < 64; kc++) {
        __pipeline_wait_prior(0);
        __syncthreads();

        if (kc + 1 < 64) {
            kv_prefetch(kc + 1, (kc + 1) & 1);
            __pipeline_commit();
        }

        uint32_t stg = (uint32_t)((kc & 1) * KV_STG * 2);
        uint32_t ka = ks_base0 + stg;
        uint32_t va = vs_base0 + stg;

        // S = Q @ K^T, fp16 accumulator
        uint32_t sh[8][2];
#pragma unroll
        for (int nt = 0; nt < 8; nt++) {
            sh[nt][0] = 0u;
            sh[nt][1] = 0u;
            uint32_t b[8];
            uint32_t base = ka + (uint32_t)(nt * 8 * KV_LD * 2);
            ldsm_x4(b, base);
            ldsm_x4(b + 4, base + 64);
            mma16816_f16(sh[nt], qf[0], b + 0);
            mma16816_f16(sh[nt], qf[1], b + 2);
            mma16816_f16(sh[nt], qf[2], b + 4);
            mma16816_f16(sh[nt], qf[3], b + 6);
        }

        // P = ex2(S); fp32 row sums
        float s0 = 0.0f, s1 = 0.0f;
#pragma unroll
        for (int nt = 0; nt < 8; nt++) {
            sh[nt][0] = ex2_f16x2(sh[nt][0]);
            sh[nt][1] = ex2_f16x2(sh[nt][1]);
            float2 f0 = __half22float2(*(__half2*)&sh[nt][0]);
            float2 f1 = __half22float2(*(__half2*)&sh[nt][1]);
            s0 += f0.x + f0.y;
            s1 += f1.x + f1.y;
        }
        s0 += __shfl_xor_sync(0xffffffffu, s0, 1);
        s0 += __shfl_xor_sync(0xffffffffu, s0, 2);
        s1 += __shfl_xor_sync(0xffffffffu, s1, 1);
        s1 += __shfl_xor_sync(0xffffffffu, s1, 2);
        lsum0 += s0;
        lsum1 += s1;

        // O += P @ V (V fetched transposed from row-major [kv][d] tile)
#pragma unroll
        for (int ks = 0; ks < 4; ks++) {
            uint32_t bv[16];
#pragma unroll
            for (int dw = 0; dw < 4; dw++)
                ldsm_x4_t(bv + dw * 4,
                          va + (uint32_t)(((ks * 16) * KV_LD + dw * 16) * 2));
            uint32_t pa[4] = { sh[2 * ks][0], sh[2 * ks][1],
                               sh[2 * ks + 1][0], sh[2 * ks + 1][1] };
#pragma unroll
            for (int nt = 0; nt < 8; nt++)
                mma16816_f32(oacc[nt], pa, bv + (nt >> 1) * 4 + (nt & 1) * 2);
        }
    }

    float inv0 = 1.0f / lsum0;
    float inv1 = 1.0f / lsum1;
    size_t ob = (size_t)(qt * 128 + w * 16 + qd) * DMODEL + h * 64 + tq * 2;
#pragma unroll
    for (int nt = 0; nt < 8; nt++) {
        __half2 v0 = __floats2half2_rn(oacc[nt][0] * inv0, oacc[nt][1] * inv0);
        __half2 v1 = __floats2half2_rn(oacc[nt][2] * inv1, oacc[nt][3] * inv1);
        *(__half2*)&oh[ob + nt * 8] = v0;
        *(__half2*)&oh[ob + (size_t)8 * DMODEL + nt * 8] = v1;
    }
}

// ------------------------- launch ---------------------------------------------
extern "C" void kernel_launch(void* const* d_in, const int* in_sizes, int n_in,
                              void* d_out, int out_size) {
    const float* x  = (const float*)d_in[0];
    const float* Wq = (const float*)d_in[1];
    const float* Wk = (const float*)d_in[2];
    const float* Wv = (const float*)d_in[3];
    const float* Wo = (const float*)d_in[4];
    float* out = (float*)d_out;

    __half *xh, *wch, *woh, *qkvh, *ah;
    float *ctab, *stab;
    cudaGetSymbolAddress((void**)&xh, g_xh);
    cudaGetSymbolAddress((void**)&wch, g_wch);
    cudaGetSymbolAddress((void**)&woh, g_woh);
    cudaGetSymbolAddress((void**)&qkvh, g_qkvh);
    cudaGetSymbolAddress((void**)&ah, g_ah);
    cudaGetSymbolAddress((void**)&ctab, g_cos);
    cudaGetSymbolAddress((void**)&stab, g_sin);

    cudaFuncSetAttribute(gemm_raw_kernel<0>,
                         cudaFuncAttributeMaxDynamicSharedMemorySize, GEMM_SMEM);
    cudaFuncSetAttribute(gemm_raw_kernel<2>,
                         cudaFuncAttributeMaxDynamicSharedMemorySize, GEMM_SMEM);
    cudaFuncSetAttribute(flash_kernel,
                         cudaFuncAttributeMaxDynamicSharedMemorySize, FLASH_SMEM);

    // fused fp16 convert + trig table
    convert_all_kernel<<<1184, 256>>>(x, Wq, Wk, Wv, Wo, xh, wch, woh);
    trig_kernel<<<512, 256>>>(ctab, stab);

    // fused QKV projection with in-epilogue RoPE -> fp16 qkvh
    gemm_raw_kernel<2><<<dim3(NQKV / 128, LQ / 128), 256, GEMM_SMEM>>>(
        xh, wch, qkvh, DMODEL, NQKV, ctab, stab);

    // attention (FA2) -> fp16 attn
    flash_kernel<<<dim3(LQ / 128, NH), 256, FLASH_SMEM>>>(qkvh, ah);

    // output projection -> f32 out
    gemm_raw_kernel<0><<<dim3(DMODEL / 128, LQ / 128), 256, GEMM_SMEM>>>(
        ah, woh, out, DMODEL, DMODEL, ctab, stab);
}

// round 15
// speedup vs baseline: 1.0178x; 1.0178x over previous
#include <cuda_runtime.h>
#include <cuda_pipeline.h>
#include <cuda_fp16.h>
#include <math.h>
#include <stdint.h>

#define LQ     4096
#define DMODEL 1024
#define NH     16
#define NKV    4
#define DHD    64
#define NQKV   1536   // 1024 q + 256 k + 256 v
#define KVD    256

// ------------------------- scratch (device globals, no allocs) ---------------
__device__ __half g_xh[LQ*DMODEL];
__device__ __half g_wch[DMODEL*NQKV];      // packed [K, Nq|Nk|Nv]
__device__ __half g_woh[DMODEL*DMODEL];
__device__ __half g_qkvh[LQ*NQKV];
__device__ __half g_ah[LQ*DMODEL];
__device__ float  g_cos[LQ*32], g_sin[LQ*32];

// ------------------------- fused fp16 convert (x + all weights) --------------
#define CV_X  (LQ*DMODEL)
#define CV_WQ (DMODEL*DMODEL)
#define CV_WK (DMODEL*256)
#define CV_TOT (CV_X + CV_WQ + 2*CV_WK + CV_WQ)

__global__ void convert_all_kernel(const float* __restrict__ x,
                                   const float* __restrict__ Wq,
                                   const float* __restrict__ Wk,
                                   const float* __restrict__ Wv,
                                   const float* __restrict__ Wo,
                                   __half* __restrict__ xh,
                                   __half* __restrict__ wch,
                                   __half* __restrict__ woh) {
    for (int i = blockIdx.x * blockDim.x + threadIdx.x; i < CV_TOT;
         i += gridDim.x * blockDim.x) {
        int j = i;
        if (j < CV_X) { xh[j] = __float2half(x[j]); continue; }
        j -= CV_X;
        if (j < CV_WQ) {
            int r = j >> 10, c = j & 1023;
            wch[(size_t)r * NQKV + c] = __float2half(Wq[j]);
            continue;
        }
        j -= CV_WQ;
        if (j < CV_WK) {
            int r = j >> 8, c = j & 255;
            wch[(size_t)r * NQKV + 1024 + c] = __float2half(Wk[j]);
            continue;
        }
        j -= CV_WK;
        if (j < CV_WK) {
            int r = j >> 8, c = j & 255;
            wch[(size_t)r * NQKV + 1280 + c] = __float2half(Wv[j]);
            continue;
        }
        j -= CV_WK;
        woh[j] = __float2half(Wo[j]);
    }
}

// ------------------------- trig table (fast-math proof) ----------------------
__global__ void trig_kernel(float* __restrict__ ct, float* __restrict__ st) {
    int idx = blockIdx.x * blockDim.x + threadIdx.x;
    if (idx >= LQ * 32) return;
    int l = idx >> 5;
    int d = idx & 31;
    double p = pow(10000.0, (double)(2 * d) / 64.0);
    float invf = (float)(1.0 / p);
    float af = __fmul_rn((float)l, invf);   // same fp32 rounding as reference
    double dv = (double)af;
    ct[idx] = (float)cos(dv);
    st[idx] = (float)sin(dv);
}

// ------------------------- raw mma / ldmatrix / ex2 helpers ------------------
__device__ __forceinline__ void mma16816_f32(float* c, const uint32_t* a,
                                             const uint32_t* b) {
    asm volatile(
        "mma.sync.aligned.m16n8k16.row.col.f32.f16.f16.f32 "
        "{%0,%1,%2,%3}, {%4,%5,%6,%7}, {%8,%9}, {%0,%1,%2,%3};"
        : "+f"(c[0]), "+f"(c[1]), "+f"(c[2]), "+f"(c[3])
        : "r"(a[0]), "r"(a[1]), "r"(a[2]), "r"(a[3]), "r"(b[0]), "r"(b[1]));
}

__device__ __forceinline__ void mma16816_f16(uint32_t* c, const uint32_t* a,
                                             const uint32_t* b) {
    asm volatile(
        "mma.sync.aligned.m16n8k16.row.col.f16.f16.f16.f16 "
        "{%0,%1}, {%2,%3,%4,%5}, {%6,%7}, {%0,%1};"
        : "+r"(c[0]), "+r"(c[1])
        : "r"(a[0]), "r"(a[1]), "r"(a[2]), "r"(a[3]), "r"(b[0]), "r"(b[1]));
}

__device__ __forceinline__ uint32_t ex2_f16x2(uint32_t v) {
    uint32_t r;
    asm("ex2.approx.f16x2 %0, %1;" : "=r"(r) : "r"(v));
    return r;
}

__device__ __forceinline__ void ldsm_x4(uint32_t* r, uint32_t saddr) {
    asm volatile(
        "ldmatrix.sync.aligned.m8n8.x4.shared.b16 {%0,%1,%2,%3}, [%4];"
        : "=r"(r[0]), "=r"(r[1]), "=r"(r[2]), "=r"(r[3]) : "r"(saddr));
}

__device__ __forceinline__ void ldsm_x4_t(uint32_t* r, uint32_t saddr) {
    asm volatile(
        "ldmatrix.sync.aligned.m8n8.x4.trans.shared.b16 {%0,%1,%2,%3}, [%4];"
        : "=r"(r[0]), "=r"(r[1]), "=r"(r[2]), "=r"(r[3]) : "r"(saddr));
}

// ------------------------- raw-mma fp16 GEMM, 128x128, BK=32, 3-stage --------
// MODE 0: float C.  MODE 2: __half C + fused RoPE epilogue.
#define GA_LD 40
#define GB_LD 136
#define GA_SZ (128*GA_LD)
#define GB_SZ (32*GB_LD)
#define GSTG  (GA_SZ + GB_SZ)
#define GEMM_SMEM (3*GSTG*(int)sizeof(__half))

template <int MODE>
__global__ __launch_bounds__(256, 2) void gemm_raw_kernel(
    const __half* __restrict__ A, const __half* __restrict__ B,
    void* __restrict__ Cv, int K, int ldn,
    const float* __restrict__ ct, const float* __restrict__ st) {
    extern __shared__ __half smem[];
    int tid = threadIdx.x;
    int w = tid >> 5;
    int lane = tid & 31;
    int qd = lane >> 2, tq = lane & 3;
    int bm = blockIdx.y * 128, bn = blockIdx.x * 128;
    int wrow = (w >> 1) * 32, wcol = (w & 1) * 64;

    int lm = lane >> 3, r8 = lane & 7;
    int aoff = (((lm & 1) << 3) + r8) * GA_LD + ((lm >> 1) << 3);
    int boff = (((lm & 1) << 3) + r8) * GB_LD + ((lm >> 1) << 3);
    uint32_t sbase = (uint32_t)__cvta_generic_to_shared(smem);

    float c[2][8][4];
#pragma unroll
    for (int mr = 0; mr < 2; mr++)
#pragma unroll
        for (int nt = 0; nt < 8; nt++)
#pragma unroll
            for (int i = 0; i < 4; i++) c[mr][nt][i] = 0.0f;

    auto prefetch = [&](int kb, int stg) {
        __half* sA = smem + stg * GSTG;
        __half* sB = sA + GA_SZ;
#pragma unroll
        for (int p = 0; p < 2; p++) {
            int i = tid + p * 256;
            int ar = i >> 2, ac = (i & 3) * 8;
            __pipeline_memcpy_async(&sA[ar * GA_LD + ac],
                                    &A[(size_t)(bm + ar) * K + kb * 32 + ac], 16);
            int br = i >> 4, bc = (i & 15) * 8;
            __pipeline_memcpy_async(&sB[br * GB_LD + bc],
                                    &B[(size_t)(kb * 32 + br) * ldn + bn + bc], 16);
        }
    };

    int nk = K / 32;
    prefetch(0, 0);
    __pipeline_commit();
    prefetch(1, 1);
    __pipeline_commit();

    for (int kb = 0; kb < nk; kb++) {
        __pipeline_wait_prior(kb + 1 < nk ? 1 : 0);
        __syncthreads();

        if (kb + 2 < nk) {
            prefetch(kb + 2, (kb + 2) % 3);
            __pipeline_commit();
        }

        uint32_t st_ = sbase + (uint32_t)((kb % 3) * GSTG * 2);
        uint32_t sa = st_;
        uint32_t sb = st_ + GA_SZ * 2;

#pragma unroll
        for (int ks = 0; ks < 2; ks++) {
            uint32_t a[2][4];
#pragma unroll
            for (int mr = 0; mr < 2; mr++)
                ldsm_x4(a[mr], sa + (uint32_t)(((wrow + mr * 16) * GA_LD +
                                                ks * 16 + aoff) * 2));
            uint32_t b[16];
#pragma unroll
            for (int nt2 = 0; nt2 < 4; nt2++)
                ldsm_x4_t(b + nt2 * 4,
                          sb + (uint32_t)(((ks * 16) * GB_LD + wcol +
                                           nt2 * 16 + boff) * 2));
#pragma unroll
            for (int mr = 0; mr < 2; mr++)
#pragma unroll
                for (int nt = 0; nt < 8; nt++)
                    mma16816_f32(c[mr][nt], a[mr],
                                 b + (nt >> 1) * 4 + (nt & 1) * 2);
        }
    }

    // fused RoPE on accumulators (MODE 2): pair (d, d+32) == tiles (nt, nt+4)
    if (MODE == 2) {
        int colbase = bn + wcol;            // 64-aligned -> one head per window
        if (colbase < 1280) {               // q or k (v windows pass through)
            const float QS = 1.4426950408889634f / 8.0f;  // log2(e)/sqrt(DH)
            float qs = (colbase < 1024) ? QS : 1.0f;
#pragma unroll
            for (int mr = 0; mr < 2; mr++) {
                int r0 = bm + wrow + mr * 16 + qd;
#pragma unroll
                for (int nt = 0; nt < 4; nt++) {
                    int d = nt * 8 + tq * 2;
#pragma unroll
                    for (int half_ = 0; half_ < 2; half_++) {
                        int r = r0 + half_ * 8;
                        int i0 = 2 * half_;
#pragma unroll
                        for (int e = 0; e < 2; e++) {
                            float cc = ct[r * 32 + d + e];
                            float ss = st[r * 32 + d + e];
                            float av = c[mr][nt][i0 + e];
                            float bv = c[mr][nt + 4][i0 + e];
                            c[mr][nt][i0 + e]     = (av * cc - bv * ss) * qs;
                            c[mr][nt + 4][i0 + e] = (bv * cc + av * ss) * qs;
                        }
                    }
                }
            }
        }
    }

#pragma unroll
    for (int mr = 0; mr < 2; mr++) {
        int r0 = bm + wrow + mr * 16 + qd;
#pragma unroll
        for (int nt = 0; nt < 8; nt++) {
            int col = bn + wcol + nt * 8 + tq * 2;
            if (MODE != 0) {
                __half* C = (__half*)Cv;
                *(__half2*)&C[(size_t)r0 * ldn + col] =
                    __floats2half2_rn(c[mr][nt][0], c[mr][nt][1]);
                *(__half2*)&C[(size_t)(r0 + 8) * ldn + col] =
                    __floats2half2_rn(c[mr][nt][2], c[mr][nt][3]);
            } else {
                float* C = (float*)Cv;
                *(float2*)&C[(size_t)r0 * ldn + col] =
                    make_float2(c[mr][nt][0], c[mr][nt][1]);
                *(float2*)&C[(size_t)(r0 + 8) * ldn + col] =
                    make_float2(c[mr][nt][2], c[mr][nt][3]);
            }
        }
    }
}

// ------------------------- attention (FA2, fused S->ex2->PV per kv-slice) ----
// Per 16-kv slice: 8 f16 S-mma -> 4 ex2.f16x2 -> 8 f32 PV-mma. No phase walls;
// row-sum shfl reduction deferred to the epilogue (linear reduction).
#define KV_LD  72
#define KV_STG (64*KV_LD)
#define FLASH_SMEM (4*KV_STG*(int)sizeof(__half))

__global__ __launch_bounds__(256, 2) void flash_kernel(
    const __half* __restrict__ qkvh, __half* __restrict__ oh) {
    extern __shared__ __half sm[];
    __half* Ks0 = sm;
    __half* Vs0 = sm + 2 * KV_STG;

    int tid = threadIdx.x;
    int w = tid >> 5;
    int lane = tid & 31;
    int qd = lane >> 2;
    int tq = lane & 3;
    int qt = blockIdx.x;
    int h = blockIdx.y;
    int kvh = h >> 2;

    int lm = lane >> 3, r8 = lane & 7;
    uint32_t koff = (uint32_t)(((r8 * KV_LD) + (lm << 3)) * 2);
    uint32_t voff = (uint32_t)(((((lm & 1) << 3) + r8) * KV_LD +
                               ((lm >> 1) << 3)) * 2);
    uint32_t ks_base0 = (uint32_t)__cvta_generic_to_shared(Ks0) + koff;
    uint32_t vs_base0 = (uint32_t)__cvta_generic_to_shared(Vs0) + voff;

    uint32_t qf[4][4];
    {
        int r0 = qt * 128 + w * 16 + qd;
        const __half* qb = qkvh + (size_t)r0 * NQKV + h * 64 + tq * 2;
#pragma unroll
        for (int ks = 0; ks < 4; ks++) {
            qf[ks][0] = *(const uint32_t*)(qb + ks * 16);
            qf[ks][1] = *(const uint32_t*)(qb + (size_t)8 * NQKV + ks * 16);
            qf[ks][2] = *(const uint32_t*)(qb + ks * 16 + 8);
            qf[ks][3] = *(const uint32_t*)(qb + (size_t)8 * NQKV + ks * 16 + 8);
        }
    }

    float oacc[8][4];
#pragma unroll
    for (int nt = 0; nt < 8; nt++)
#pragma unroll
        for (int i = 0; i < 4; i++) oacc[nt][i] = 0.0f;
    float lsum0 = 0.0f, lsum1 = 0.0f;   // lane-local partials (reduced at end)

    auto kv_prefetch = [&](int kc, int s) {
        __half* Ks_ = Ks0 + s * KV_STG;
        __half* Vs_ = Vs0 + s * KV_STG;
#pragma unroll
        for (int p = 0; p < 2; p++) {
            int i = tid + p * 256;
            int r = i >> 3, c8 = (i & 7) * 8;
            size_t rb = (size_t)(kc * 64 + r) * NQKV + 1024 + kvh * 64 + c8;
            __pipeline_memcpy_async(&Ks_[r * KV_LD + c8], &qkvh[rb], 16);
            __pipeline_memcpy_async(&Vs_[r * KV_LD + c8], &qkvh[rb + 256], 16);
        }
    };

    kv_prefetch(0, 0);
    __pipeline_commit();

    for (int kc = 0; kc < 64; kc++) {
        __pipeline_wait_prior(0);
        __syncthreads();

        if (kc + 1 < 64) {
            kv_prefetch(kc + 1, (kc + 1) & 1);
            __pipeline_commit();
        }

        uint32_t stg = (uint32_t)((kc & 1) * KV_STG * 2);
        uint32_t ka = ks_base0 + stg;
        uint32_t va = vs_base0 + stg;

        // fused per 16-kv slice: S (2 n-tiles) -> ex2 -> PV into all 8 d-tiles
#pragma unroll
        for (int ks = 0; ks < 4; ks++) {
            // S n-tiles 2ks, 2ks+1 (fp16 accumulators)
            uint32_t s0[2] = {0u, 0u}, s1[2] = {0u, 0u};
            {
                uint32_t bk[8];
                uint32_t b0 = ka + (uint32_t)((2 * ks) * 8 * KV_LD * 2);
                ldsm_x4(bk, b0);
                ldsm_x4(bk + 4, b0 + 64);
                mma16816_f16(s0, qf[0], bk + 0);
                mma16816_f16(s0, qf[1], bk + 2);
                mma16816_f16(s0, qf[2], bk + 4);
                mma16816_f16(s0, qf[3], bk + 6);
                uint32_t b1 = ka + (uint32_t)((2 * ks + 1) * 8 * KV_LD * 2);
                ldsm_x4(bk, b1);
                ldsm_x4(bk + 4, b1 + 64);
                mma16816_f16(s1, qf[0], bk + 0);
                mma16816_f16(s1, qf[1], bk + 2);
                mma16816_f16(s1, qf[2], bk + 4);
                mma16816_f16(s1, qf[3], bk + 6);
            }

            // P = ex2(S); lane-local fp32 partial sums
            s0[0] = ex2_f16x2(s0[0]);
            s0[1] = ex2_f16x2(s0[1]);
            s1[0] = ex2_f16x2(s1[0]);
            s1[1] = ex2_f16x2(s1[1]);
            {
                float2 a0 = __half22float2(*(__half2*)&s0[0]);
                float2 a1 = __half22float2(*(__half2*)&s0[1]);
                float2 a2 = __half22float2(*(__half2*)&s1[0]);
                float2 a3 = __half22float2(*(__half2*)&s1[1]);
                lsum0 += a0.x + a0.y + a2.x + a2.y;
                lsum1 += a1.x + a1.y + a3.x + a3.y;
            }

            // PV: this slice's P (16 kv) x V(16 kv, 64 d)
            uint32_t pa[4] = { s0[0], s0[1], s1[0], s1[1] };
            uint32_t bv[16];
#pragma unroll
            for (int dw = 0; dw < 4; dw++)
                ldsm_x4_t(bv + dw * 4,
                          va + (uint32_t)(((ks * 16) * KV_LD + dw * 16) * 2));
#pragma unroll
            for (int nt = 0; nt < 8; nt++)
                mma16816_f32(oacc[nt], pa, bv + (nt >> 1) * 4 + (nt & 1) * 2);
        }
    }

    // deferred row-sum reduction (linear; order change only affects fp32 ~1e-7)
    lsum0 += __shfl_xor_sync(0xffffffffu, lsum0, 1);
    lsum0 += __shfl_xor_sync(0xffffffffu, lsum0, 2);
    lsum1 += __shfl_xor_sync(0xffffffffu, lsum1, 1);
    lsum1 += __shfl_xor_sync(0xffffffffu, lsum1, 2);

    float inv0 = 1.0f / lsum0;
    float inv1 = 1.0f / lsum1;
    size_t ob = (size_t)(qt * 128 + w * 16 + qd) * DMODEL + h * 64 + tq * 2;
#pragma unroll
    for (int nt = 0; nt < 8; nt++) {
        __half2 v0 = __floats2half2_rn(oacc[nt][0] * inv0, oacc[nt][1] * inv0);
        __half2 v1 = __floats2half2_rn(oacc[nt][2] * inv1, oacc[nt][3] * inv1);
        *(__half2*)&oh[ob + nt * 8] = v0;
        *(__half2*)&oh[ob + (size_t)8 * DMODEL + nt * 8] = v1;
    }
}

// ------------------------- launch ---------------------------------------------
extern "C" void kernel_launch(void* const* d_in, const int* in_sizes, int n_in,
                              void* d_out, int out_size) {
    const float* x  = (const float*)d_in[0];
    const float* Wq = (const float*)d_in[1];
    const float* Wk = (const float*)d_in[2];
    const float* Wv = (const float*)d_in[3];
    const float* Wo = (const float*)d_in[4];
    float* out = (float*)d_out;

    __half *xh, *wch, *woh, *qkvh, *ah;
    float *ctab, *stab;
    cudaGetSymbolAddress((void**)&xh, g_xh);
    cudaGetSymbolAddress((void**)&wch, g_wch);
    cudaGetSymbolAddress((void**)&woh, g_woh);
    cudaGetSymbolAddress((void**)&qkvh, g_qkvh);
    cudaGetSymbolAddress((void**)&ah, g_ah);
    cudaGetSymbolAddress((void**)&ctab, g_cos);
    cudaGetSymbolAddress((void**)&stab, g_sin);

    cudaFuncSetAttribute(gemm_raw_kernel<0>,
                         cudaFuncAttributeMaxDynamicSharedMemorySize, GEMM_SMEM);
    cudaFuncSetAttribute(gemm_raw_kernel<2>,
                         cudaFuncAttributeMaxDynamicSharedMemorySize, GEMM_SMEM);
    cudaFuncSetAttribute(flash_kernel,
                         cudaFuncAttributeMaxDynamicSharedMemorySize, FLASH_SMEM);

    // fused fp16 convert + trig table
    convert_all_kernel<<<1184, 256>>>(x, Wq, Wk, Wv, Wo, xh, wch, woh);
    trig_kernel<<<512, 256>>>(ctab, stab);

    // fused QKV projection with in-epilogue RoPE -> fp16 qkvh
    gemm_raw_kernel<2><<<dim3(NQKV / 128, LQ / 128), 256, GEMM_SMEM>>>(
        xh, wch, qkvh, DMODEL, NQKV, ctab, stab);

    // attention (FA2, fused slice pipeline) -> fp16 attn
    flash_kernel<<<dim3(LQ / 128, NH), 256, FLASH_SMEM>>>(qkvh, ah);

    // output projection -> f32 out
    gemm_raw_kernel<0><<<dim3(DMODEL / 128, LQ / 128), 256, GEMM_SMEM>>>(
        ah, woh, out, DMODEL, DMODEL, ctab, stab);
}

// round 16
// speedup vs baseline: 1.0782x; 1.0594x over previous
#include <cuda_runtime.h>
#include <cuda_pipeline.h>
#include <cuda_fp16.h>
#include <math.h>
#include <stdint.h>

#define LQ     4096
#define DMODEL 1024
#define NH     16
#define NKV    4
#define DHD    64
#define NQKV   1536   // 1024 q + 256 k + 256 v
#define KVD    256

// ------------------------- scratch (device globals, no allocs) ---------------
__device__ __half g_xh[LQ*DMODEL];
__device__ __half g_wch[DMODEL*NQKV];      // packed [K, Nq|Nk|Nv]
__device__ __half g_woh[DMODEL*DMODEL];
__device__ __half g_qkvh[LQ*NQKV];
__device__ __half g_ah[LQ*DMODEL];
__device__ float  g_cos[LQ*32], g_sin[LQ*32];

// ------------------------- fused fp16 convert (x + all weights) --------------
#define CV_X  (LQ*DMODEL)
#define CV_WQ (DMODEL*DMODEL)
#define CV_WK (DMODEL*256)
#define CV_TOT (CV_X + CV_WQ + 2*CV_WK + CV_WQ)

__global__ void convert_all_kernel(const float* __restrict__ x,
                                   const float* __restrict__ Wq,
                                   const float* __restrict__ Wk,
                                   const float* __restrict__ Wv,
                                   const float* __restrict__ Wo,
                                   __half* __restrict__ xh,
                                   __half* __restrict__ wch,
                                   __half* __restrict__ woh) {
    for (int i = blockIdx.x * blockDim.x + threadIdx.x; i < CV_TOT;
         i += gridDim.x * blockDim.x) {
        int j = i;
        if (j < CV_X) { xh[j] = __float2half(x[j]); continue; }
        j -= CV_X;
        if (j < CV_WQ) {
            int r = j >> 10, c = j & 1023;
            wch[(size_t)r * NQKV + c] = __float2half(Wq[j]);
            continue;
        }
        j -= CV_WQ;
        if (j < CV_WK) {
            int r = j >> 8, c = j & 255;
            wch[(size_t)r * NQKV + 1024 + c] = __float2half(Wk[j]);
            continue;
        }
        j -= CV_WK;
        if (j < CV_WK) {
            int r = j >> 8, c = j & 255;
            wch[(size_t)r * NQKV + 1280 + c] = __float2half(Wv[j]);
            continue;
        }
        j -= CV_WK;
        woh[j] = __float2half(Wo[j]);
    }
}

// ------------------------- trig table (fast-math proof) ----------------------
__global__ void trig_kernel(float* __restrict__ ct, float* __restrict__ st) {
    int idx = blockIdx.x * blockDim.x + threadIdx.x;
    if (idx >= LQ * 32) return;
    int l = idx >> 5;
    int d = idx & 31;
    double p = pow(10000.0, (double)(2 * d) / 64.0);
    float invf = (float)(1.0 / p);
    float af = __fmul_rn((float)l, invf);   // same fp32 rounding as reference
    double dv = (double)af;
    ct[idx] = (float)cos(dv);
    st[idx] = (float)sin(dv);
}

// ------------------------- raw mma / ldmatrix / ex2 helpers ------------------
__device__ __forceinline__ void mma16816_f32(float* c, const uint32_t* a,
                                             const uint32_t* b) {
    asm volatile(
        "mma.sync.aligned.m16n8k16.row.col.f32.f16.f16.f32 "
        "{%0,%1,%2,%3}, {%4,%5,%6,%7}, {%8,%9}, {%0,%1,%2,%3};"
        : "+f"(c[0]), "+f"(c[1]), "+f"(c[2]), "+f"(c[3])
        : "r"(a[0]), "r"(a[1]), "r"(a[2]), "r"(a[3]), "r"(b[0]), "r"(b[1]));
}

__device__ __forceinline__ void mma16816_f16(uint32_t* c, const uint32_t* a,
                                             const uint32_t* b) {
    asm volatile(
        "mma.sync.aligned.m16n8k16.row.col.f16.f16.f16.f16 "
        "{%0,%1}, {%2,%3,%4,%5}, {%6,%7}, {%0,%1};"
        : "+r"(c[0]), "+r"(c[1])
        : "r"(a[0]), "r"(a[1]), "r"(a[2]), "r"(a[3]), "r"(b[0]), "r"(b[1]));
}

__device__ __forceinline__ uint32_t ex2_f16x2(uint32_t v) {
    uint32_t r;
    asm("ex2.approx.f16x2 %0, %1;" : "=r"(r) : "r"(v));
    return r;
}

__device__ __forceinline__ void ldsm_x4(uint32_t* r, uint32_t saddr) {
    asm volatile(
        "ldmatrix.sync.aligned.m8n8.x4.shared.b16 {%0,%1,%2,%3}, [%4];"
        : "=r"(r[0]), "=r"(r[1]), "=r"(r[2]), "=r"(r[3]) : "r"(saddr));
}

__device__ __forceinline__ void ldsm_x4_t(uint32_t* r, uint32_t saddr) {
    asm volatile(
        "ldmatrix.sync.aligned.m8n8.x4.trans.shared.b16 {%0,%1,%2,%3}, [%4];"
        : "=r"(r[0]), "=r"(r[1]), "=r"(r[2]), "=r"(r[3]) : "r"(saddr));
}

// ------------------------- raw-mma fp16 GEMM, 128x128, BK=32, 3-stage --------
// MODE 0: float C.  MODE 2: __half C + fused RoPE epilogue.
#define GA_LD 40
#define GB_LD 136
#define GA_SZ (128*GA_LD)
#define GB_SZ (32*GB_LD)
#define GSTG  (GA_SZ + GB_SZ)
#define GEMM_SMEM (3*GSTG*(int)sizeof(__half))

template <int MODE>
__global__ __launch_bounds__(256, 2) void gemm_raw_kernel(
    const __half* __restrict__ A, const __half* __restrict__ B,
    void* __restrict__ Cv, int K, int ldn,
    const float* __restrict__ ct, const float* __restrict__ st) {
    extern __shared__ __half smem[];
    int tid = threadIdx.x;
    int w = tid >> 5;
    int lane = tid & 31;
    int qd = lane >> 2, tq = lane & 3;
    int bm = blockIdx.y * 128, bn = blockIdx.x * 128;
    int wrow = (w >> 1) * 32, wcol = (w & 1) * 64;

    int lm = lane >> 3, r8 = lane & 7;
    int aoff = (((lm & 1) << 3) + r8) * GA_LD + ((lm >> 1) << 3);
    int boff = (((lm & 1) << 3) + r8) * GB_LD + ((lm >> 1) << 3);
    uint32_t sbase = (uint32_t)__cvta_generic_to_shared(smem);

    float c[2][8][4];
#pragma unroll
    for (int mr = 0; mr < 2; mr++)
#pragma unroll
        for (int nt = 0; nt < 8; nt++)
#pragma unroll
            for (int i = 0; i < 4; i++) c[mr][nt][i] = 0.0f;

    auto prefetch = [&](int kb, int stg) {
        __half* sA = smem + stg * GSTG;
        __half* sB = sA + GA_SZ;
#pragma unroll
        for (int p = 0; p < 2; p++) {
            int i = tid + p * 256;
            int ar = i >> 2, ac = (i & 3) * 8;
            __pipeline_memcpy_async(&sA[ar * GA_LD + ac],
                                    &A[(size_t)(bm + ar) * K + kb * 32 + ac], 16);
            int br = i >> 4, bc = (i & 15) * 8;
            __pipeline_memcpy_async(&sB[br * GB_LD + bc],
                                    &B[(size_t)(kb * 32 + br) * ldn + bn + bc], 16);
        }
    };

    int nk = K / 32;
    prefetch(0, 0);
    __pipeline_commit();
    prefetch(1, 1);
    __pipeline_commit();

    for (int kb = 0; kb < nk; kb++) {
        __pipeline_wait_prior(kb + 1 < nk ? 1 : 0);
        __syncthreads();

        if (kb + 2 < nk) {
            prefetch(kb + 2, (kb + 2) % 3);
            __pipeline_commit();
        }

        uint32_t st_ = sbase + (uint32_t)((kb % 3) * GSTG * 2);
        uint32_t sa = st_;
        uint32_t sb = st_ + GA_SZ * 2;

#pragma unroll
        for (int ks = 0; ks < 2; ks++) {
            uint32_t a[2][4];
#pragma unroll
            for (int mr = 0; mr < 2; mr++)
                ldsm_x4(a[mr], sa + (uint32_t)(((wrow + mr * 16) * GA_LD +
                                                ks * 16 + aoff) * 2));
            uint32_t b[16];
#pragma unroll
            for (int nt2 = 0; nt2 < 4; nt2++)
                ldsm_x4_t(b + nt2 * 4,
                          sb + (uint32_t)(((ks * 16) * GB_LD + wcol +
                                           nt2 * 16 + boff) * 2));
#pragma unroll
            for (int mr = 0; mr < 2; mr++)
#pragma unroll
                for (int nt = 0; nt < 8; nt++)
                    mma16816_f32(c[mr][nt], a[mr],
                                 b + (nt >> 1) * 4 + (nt & 1) * 2);
        }
    }

    // fused RoPE on accumulators (MODE 2): pair (d, d+32) == tiles (nt, nt+4)
    if (MODE == 2) {
        int colbase = bn + wcol;            // 64-aligned -> one head per window
        if (colbase < 1280) {               // q or k (v windows pass through)
            const float QS = 1.4426950408889634f / 8.0f;  // log2(e)/sqrt(DH)
            float qs = (colbase < 1024) ? QS : 1.0f;
#pragma unroll
            for (int mr = 0; mr < 2; mr++) {
                int r0 = bm + wrow + mr * 16 + qd;
#pragma unroll
                for (int nt = 0; nt < 4; nt++) {
                    int d = nt * 8 + tq * 2;
#pragma unroll
                    for (int half_ = 0; half_ < 2; half_++) {
                        int r = r0 + half_ * 8;
                        int i0 = 2 * half_;
#pragma unroll
                        for (int e = 0; e < 2; e++) {
                            float cc = ct[r * 32 + d + e];
                            float ss = st[r * 32 + d + e];
                            float av = c[mr][nt][i0 + e];
                            float bv = c[mr][nt + 4][i0 + e];
                            c[mr][nt][i0 + e]     = (av * cc - bv * ss) * qs;
                            c[mr][nt + 4][i0 + e] = (bv * cc + av * ss) * qs;
                        }
                    }
                }
            }
        }
    }

#pragma unroll
    for (int mr = 0; mr < 2; mr++) {
        int r0 = bm + wrow + mr * 16 + qd;
#pragma unroll
        for (int nt = 0; nt < 8; nt++) {
            int col = bn + wcol + nt * 8 + tq * 2;
            if (MODE != 0) {
                __half* C = (__half*)Cv;
                *(__half2*)&C[(size_t)r0 * ldn + col] =
                    __floats2half2_rn(c[mr][nt][0], c[mr][nt][1]);
                *(__half2*)&C[(size_t)(r0 + 8) * ldn + col] =
                    __floats2half2_rn(c[mr][nt][2], c[mr][nt][3]);
            } else {
                float* C = (float*)Cv;
                *(float2*)&C[(size_t)r0 * ldn + col] =
                    make_float2(c[mr][nt][0], c[mr][nt][1]);
                *(float2*)&C[(size_t)(r0 + 8) * ldn + col] =
                    make_float2(c[mr][nt][2], c[mr][nt][3]);
            }
        }
    }
}

// ------------------------- attention (FA2, 32 q rows per warp) ---------------
// 128 threads / 4 warps; each warp owns TWO m16 tiles (32 q rows) so every
// K/V B-fragment feeds 2 MMAs -> half the LDSM traffic per tensor op.
#define KV_LD  72
#define KV_STG (64*KV_LD)
#define FLASH_SMEM (4*KV_STG*(int)sizeof(__half))

__global__ __launch_bounds__(128, 3) void flash_kernel(
    const __half* __restrict__ qkvh, __half* __restrict__ oh) {
    extern __shared__ __half sm[];
    __half* Ks0 = sm;
    __half* Vs0 = sm + 2 * KV_STG;

    int tid = threadIdx.x;
    int w = tid >> 5;
    int lane = tid & 31;
    int qd = lane >> 2;
    int tq = lane & 3;
    int qt = blockIdx.x;
    int h = blockIdx.y;
    int kvh = h >> 2;

    int lm = lane >> 3, r8 = lane & 7;
    uint32_t koff = (uint32_t)(((r8 * KV_LD) + (lm << 3)) * 2);
    uint32_t voff = (uint32_t)(((((lm & 1) << 3) + r8) * KV_LD +
                               ((lm >> 1) << 3)) * 2);
    uint32_t ks_base0 = (uint32_t)__cvta_generic_to_shared(Ks0) + koff;
    uint32_t vs_base0 = (uint32_t)__cvta_generic_to_shared(Vs0) + voff;

    // Q fragments: 32 rows per warp (2 m16 tiles), registers for whole kernel
    uint32_t qf[2][4][4];
#pragma unroll
    for (int mr = 0; mr < 2; mr++) {
        int r0 = qt * 128 + w * 32 + mr * 16 + qd;
        const __half* qb = qkvh + (size_t)r0 * NQKV + h * 64 + tq * 2;
#pragma unroll
        for (int ks = 0; ks < 4; ks++) {
            qf[mr][ks][0] = *(const uint32_t*)(qb + ks * 16);
            qf[mr][ks][1] = *(const uint32_t*)(qb + (size_t)8 * NQKV + ks * 16);
            qf[mr][ks][2] = *(const uint32_t*)(qb + ks * 16 + 8);
            qf[mr][ks][3] = *(const uint32_t*)(qb + (size_t)8 * NQKV + ks * 16 + 8);
        }
    }

    float oacc[2][8][4];
#pragma unroll
    for (int mr = 0; mr < 2; mr++)
#pragma unroll
        for (int nt = 0; nt < 8; nt++)
#pragma unroll
            for (int i = 0; i < 4; i++) oacc[mr][nt][i] = 0.0f;
    float lsum[2][2] = {{0.0f, 0.0f}, {0.0f, 0.0f}};

    auto kv_prefetch = [&](int kc, int s) {
        __half* Ks_ = Ks0 + s * KV_STG;
        __half* Vs_ = Vs0 + s * KV_STG;
#pragma unroll
        for (int p = 0; p < 4; p++) {
            int i = tid + p * 128;
            int r = i >> 3, c8 = (i & 7) * 8;
            size_t rb = (size_t)(kc * 64 + r) * NQKV + 1024 + kvh * 64 + c8;
            __pipeline_memcpy_async(&Ks_[r * KV_LD + c8], &qkvh[rb], 16);
            __pipeline_memcpy_async(&Vs_[r * KV_LD + c8], &qkvh[rb + 256], 16);
        }
    };

    kv_prefetch(0, 0);
    __pipeline_commit();

    for (int kc = 0; kc < 64; kc++) {
        __pipeline_wait_prior(0);
        __syncthreads();

        if (kc + 1 < 64) {
            kv_prefetch(kc + 1, (kc + 1) & 1);
            __pipeline_commit();
        }

        uint32_t stg = (uint32_t)((kc & 1) * KV_STG * 2);
        uint32_t ka = ks_base0 + stg;
        uint32_t va = vs_base0 + stg;

        // fused per 16-kv slice: S (2 n-tiles x 2 m-tiles) -> ex2 -> PV
#pragma unroll
        for (int ks = 0; ks < 4; ks++) {
            uint32_t s0[2][2], s1[2][2];   // [mr][frag]
#pragma unroll
            for (int mr = 0; mr < 2; mr++) {
                s0[mr][0] = 0u; s0[mr][1] = 0u;
                s1[mr][0] = 0u; s1[mr][1] = 0u;
            }
            {
                uint32_t bk[8];
                uint32_t b0 = ka + (uint32_t)((2 * ks) * 8 * KV_LD * 2);
                ldsm_x4(bk, b0);
                ldsm_x4(bk + 4, b0 + 64);
#pragma unroll
                for (int mr = 0; mr < 2; mr++) {
                    mma16816_f16(s0[mr], qf[mr][0], bk + 0);
                    mma16816_f16(s0[mr], qf[mr][1], bk + 2);
                    mma16816_f16(s0[mr], qf[mr][2], bk + 4);
                    mma16816_f16(s0[mr], qf[mr][3], bk + 6);
                }
                uint32_t b1 = ka + (uint32_t)((2 * ks + 1) * 8 * KV_LD * 2);
                ldsm_x4(bk, b1);
                ldsm_x4(bk + 4, b1 + 64);
#pragma unroll
                for (int mr = 0; mr < 2; mr++) {
                    mma16816_f16(s1[mr], qf[mr][0], bk + 0);
                    mma16816_f16(s1[mr], qf[mr][1], bk + 2);
                    mma16816_f16(s1[mr], qf[mr][2], bk + 4);
                    mma16816_f16(s1[mr], qf[mr][3], bk + 6);
                }
            }

            // P = ex2(S); lane-local fp32 partial sums
#pragma unroll
            for (int mr = 0; mr < 2; mr++) {
                s0[mr][0] = ex2_f16x2(s0[mr][0]);
                s0[mr][1] = ex2_f16x2(s0[mr][1]);
                s1[mr][0] = ex2_f16x2(s1[mr][0]);
                s1[mr][1] = ex2_f16x2(s1[mr][1]);
                float2 a0 = __half22float2(*(__half2*)&s0[mr][0]);
                float2 a1 = __half22float2(*(__half2*)&s0[mr][1]);
                float2 a2 = __half22float2(*(__half2*)&s1[mr][0]);
                float2 a3 = __half22float2(*(__half2*)&s1[mr][1]);
                lsum[mr][0] += a0.x + a0.y + a2.x + a2.y;
                lsum[mr][1] += a1.x + a1.y + a3.x + a3.y;
            }

            // PV: V fragments loaded once, used by both m-tiles
            uint32_t bv[16];
#pragma unroll
            for (int dw = 0; dw < 4; dw++)
                ldsm_x4_t(bv + dw * 4,
                          va + (uint32_t)(((ks * 16) * KV_LD + dw * 16) * 2));
#pragma unroll
            for (int mr = 0; mr < 2; mr++) {
                uint32_t pa[4] = { s0[mr][0], s0[mr][1], s1[mr][0], s1[mr][1] };
#pragma unroll
                for (int nt = 0; nt < 8; nt++)
                    mma16816_f32(oacc[mr][nt], pa,
                                 bv + (nt >> 1) * 4 + (nt & 1) * 2);
            }
        }
    }

    // deferred row-sum reduction + store
#pragma unroll
    for (int mr = 0; mr < 2; mr++) {
        float l0 = lsum[mr][0], l1 = lsum[mr][1];
        l0 += __shfl_xor_sync(0xffffffffu, l0, 1);
        l0 += __shfl_xor_sync(0xffffffffu, l0, 2);
        l1 += __shfl_xor_sync(0xffffffffu, l1, 1);
        l1 += __shfl_xor_sync(0xffffffffu, l1, 2);
        float inv0 = 1.0f / l0;
        float inv1 = 1.0f / l1;
        size_t ob = (size_t)(qt * 128 + w * 32 + mr * 16 + qd) * DMODEL +
                    h * 64 + tq * 2;
#pragma unroll
        for (int nt = 0; nt < 8; nt++) {
            __half2 v0 = __floats2half2_rn(oacc[mr][nt][0] * inv0,
                                           oacc[mr][nt][1] * inv0);
            __half2 v1 = __floats2half2_rn(oacc[mr][nt][2] * inv1,
                                           oacc[mr][nt][3] * inv1);
            *(__half2*)&oh[ob + nt * 8] = v0;
            *(__half2*)&oh[ob + (size_t)8 * DMODEL + nt * 8] = v1;
        }
    }
}

// ------------------------- launch ---------------------------------------------
extern "C" void kernel_launch(void* const* d_in, const int* in_sizes, int n_in,
                              void* d_out, int out_size) {
    const float* x  = (const float*)d_in[0];
    const float* Wq = (const float*)d_in[1];
    const float* Wk = (const float*)d_in[2];
    const float* Wv = (const float*)d_in[3];
    const float* Wo = (const float*)d_in[4];
    float* out = (float*)d_out;

    __half *xh, *wch, *woh, *qkvh, *ah;
    float *ctab, *stab;
    cudaGetSymbolAddress((void**)&xh, g_xh);
    cudaGetSymbolAddress((void**)&wch, g_wch);
    cudaGetSymbolAddress((void**)&woh, g_woh);
    cudaGetSymbolAddress((void**)&qkvh, g_qkvh);
    cudaGetSymbolAddress((void**)&ah, g_ah);
    cudaGetSymbolAddress((void**)&ctab, g_cos);
    cudaGetSymbolAddress((void**)&stab, g_sin);

    cudaFuncSetAttribute(gemm_raw_kernel<0>,
                         cudaFuncAttributeMaxDynamicSharedMemorySize, GEMM_SMEM);
    cudaFuncSetAttribute(gemm_raw_kernel<2>,
                         cudaFuncAttributeMaxDynamicSharedMemorySize, GEMM_SMEM);
    cudaFuncSetAttribute(flash_kernel,
                         cudaFuncAttributeMaxDynamicSharedMemorySize, FLASH_SMEM);

    // fused fp16 convert + trig table
    convert_all_kernel<<<1184, 256>>>(x, Wq, Wk, Wv, Wo, xh, wch, woh);
    trig_kernel<<<512, 256>>>(ctab, stab);

    // fused QKV projection with in-epilogue RoPE -> fp16 qkvh
    gemm_raw_kernel<2><<<dim3(NQKV / 128, LQ / 128), 256, GEMM_SMEM>>>(
        xh, wch, qkvh, DMODEL, NQKV, ctab, stab);

    // attention (FA2, 32 rows/warp) -> fp16 attn
    flash_kernel<<<dim3(LQ / 128, NH), 128, FLASH_SMEM>>>(qkvh, ah);

    // output projection -> f32 out
    gemm_raw_kernel<0><<<dim3(DMODEL / 128, LQ / 128), 256, GEMM_SMEM>>>(
        ah, woh, out, DMODEL, DMODEL, ctab, stab);
}